// round 8
// baseline (speedup 1.0000x reference)
#include <cuda_runtime.h>

#define Nn    4096
#define Bb    4
#define Kk    8
#define BN    (Bb * Nn)         // 16384 points per cloud
#define NQ    4                 // candidate-dimension split factor
#define PPB   256               // points per block
#define TPB   (PPB * NQ)        // 1024 threads
#define QLEN  (Nn / NQ)         // 1024 candidates per thread
#define CB    64                // combine blocks (BN / 256)
#define CTPB  256
#define EPSF  1e-12f

// ---- device scratch (SoA, coalesced) ----
__device__ float g_dens[2 * BN];
__device__ float g_cov [2 * 6 * BN];
__device__ float g_nv  [2 * Kk * 3 * BN];
__device__ float g_part[3 * CB];

// Scan QLEN candidates starting at j0, keep 9 smallest squared distances
// (ascending; ties -> lower index, guaranteed by monotone j + strict <).
__device__ __forceinline__ void scan9(const float4* __restrict__ s, int j0,
                                      float px, float py, float pz, float sq,
                                      float bd[9], int bi[9]) {
#pragma unroll
    for (int t = 0; t < 9; t++) { bd[t] = 3.4e38f; bi[t] = 0; }
    const float m2x = -2.0f * px, m2y = -2.0f * py, m2z = -2.0f * pz;
    float thr = 3.4e38f;                       // = bd[8] - sq
    const int jend = j0 + QLEN;
#pragma unroll 4
    for (int j = j0; j < jend; j++) {
        float4 q  = s[j];
        float d2p = fmaf(m2x, q.x, fmaf(m2y, q.y, fmaf(m2z, q.z, q.w)));
        bool hit = d2p < thr;
        if (__any_sync(0xffffffffu, hit)) {
            float v = d2p + sq;
            bool c[9];
#pragma unroll
            for (int t = 0; t < 9; t++) c[t] = v < bd[t];
#pragma unroll
            for (int t = 8; t >= 1; t--) {
                bd[t] = c[t] ? (c[t-1] ? bd[t-1] : v) : bd[t];
                bi[t] = c[t] ? (c[t-1] ? bi[t-1] : j) : bi[t];
            }
            bd[0] = c[0] ? v : bd[0];
            bi[0] = c[0] ? j : bi[0];
            thr = bd[8] - sq;
        }
    }
}

// Merge sorted 9-list (ed,ei) into (bd,bi); ties prefer (bd,bi) (lower index).
__device__ __forceinline__ void merge9(float bd[9], int bi[9],
                                       const float* __restrict__ ld,
                                       const int*   __restrict__ li) {
    float ed[9]; int ei[9];
#pragma unroll
    for (int t = 0; t < 9; t++) { ed[t] = ld[t]; ei[t] = li[t]; }
    float od[9]; int oi[9];
#pragma unroll
    for (int r = 0; r < 9; r++) {
        bool ta = bd[0] <= ed[0];
        od[r] = ta ? bd[0] : ed[0];
        oi[r] = ta ? bi[0] : ei[0];
#pragma unroll
        for (int t = 0; t < 8; t++) {
            bd[t] = ta ? bd[t+1] : bd[t];
            bi[t] = ta ? bi[t+1] : bi[t];
            ed[t] = ta ? ed[t]   : ed[t+1];
            ei[t] = ta ? ei[t]   : ei[t+1];
        }
        bd[8] = ta ? 3.4e38f : bd[8];
        ed[8] = ta ? ed[8]   : 3.4e38f;
    }
#pragma unroll
    for (int t = 0; t < 9; t++) { bd[t] = od[t]; bi[t] = oi[t]; }
}

// Block: 256 points of one (batch, cloud), 4 threads/point (candidate quarters).
__global__ void __launch_bounds__(TPB)
knn_scan_kernel(const float* __restrict__ pred, const float* __restrict__ target) {
    extern __shared__ char smem_raw[];
    float4* sc   = (float4*)smem_raw;                         // [Nn] cloud
    float*  lstd = (float*)(smem_raw + Nn * sizeof(float4));  // [3][PPB][9]
    int*    lsti = (int*)(lstd + 3 * PPB * 9);                // [3][PPB][9]

    const int tid = threadIdx.x;
    const int b   = blockIdx.y;
    const int c   = blockIdx.z;              // 0 = pred, 1 = target
    const int pl  = tid & (PPB - 1);         // local point
    const int qt  = tid >> 8;                // quarter 0..3 (warp-uniform)

    const float* src = (c == 0 ? pred : target) + (size_t)b * Nn * 3;
    for (int p = tid; p < Nn; p += TPB) {
        float x = src[3*p+0], y = src[3*p+1], z = src[3*p+2];
        sc[p] = make_float4(x, y, z, fmaf(x, x, fmaf(y, y, z*z)));
    }
    __syncthreads();

    const int i  = blockIdx.x * PPB + pl;
    const float4 Pi = sc[i];

    float bd[9]; int bi[9];
    scan9(sc, qt * QLEN, Pi.x, Pi.y, Pi.z, Pi.w, bd, bi);

    // quarters 1..3 publish their sorted lists (stride-9 -> conflict-free)
    if (qt != 0) {
        float* dd = lstd + ((qt - 1) * PPB + pl) * 9;
        int*   ii = lsti + ((qt - 1) * PPB + pl) * 9;
#pragma unroll
        for (int t = 0; t < 9; t++) { dd[t] = bd[t]; ii[t] = bi[t]; }
    }
    __syncthreads();
    if (qt != 0) return;

    // quarter 0 merges Q1, Q2, Q3 (index order preserved for tie stability)
#pragma unroll
    for (int m = 0; m < 3; m++) {
        merge9(bd, bi, lstd + (m * PPB + pl) * 9, lsti + (m * PPB + pl) * 9);
    }

    // ---- epilogue: density, covariance, normalized neighbor vectors ----
    const int base = b * Nn + i;
    float dens = 0.f;
    float cxx = 0.f, cyy = 0.f, czz = 0.f, cxy = 0.f, cxz = 0.f, cyz = 0.f;
#pragma unroll
    for (int k = 0; k < Kk; k++) {
        dens += sqrtf(fmaxf(bd[k+1], EPSF));
        float4 q = sc[bi[k+1]];
        float vx = q.x - Pi.x, vy = q.y - Pi.y, vz = q.z - Pi.z;
        cxx = fmaf(vx, vx, cxx); cyy = fmaf(vy, vy, cyy); czz = fmaf(vz, vz, czz);
        cxy = fmaf(vx, vy, cxy); cxz = fmaf(vx, vz, cxz); cyz = fmaf(vy, vz, cyz);
        float nrm = sqrtf(fmaf(vx, vx, fmaf(vy, vy, vz * vz)));
        float inv = 1.0f / fmaxf(nrm, EPSF);
        g_nv[((c*Kk + k)*3 + 0)*BN + base] = vx * inv;
        g_nv[((c*Kk + k)*3 + 1)*BN + base] = vy * inv;
        g_nv[((c*Kk + k)*3 + 2)*BN + base] = vz * inv;
    }
    g_dens[c*BN + base]        = dens * 0.125f;
    g_cov[(c*6 + 0)*BN + base] = cxx * 0.125f;
    g_cov[(c*6 + 1)*BN + base] = cyy * 0.125f;
    g_cov[(c*6 + 2)*BN + base] = czz * 0.125f;
    g_cov[(c*6 + 3)*BN + base] = cxy * 0.125f;
    g_cov[(c*6 + 4)*BN + base] = cxz * 0.125f;
    g_cov[(c*6 + 5)*BN + base] = cyz * 0.125f;
}

// Pair pred/target stats per point, partial-reduce per block.
__global__ void __launch_bounds__(CTPB)
combine_kernel() {
    const int tid = threadIdx.x;
    const int idx = blockIdx.x * CTPB + tid;

    float dd = g_dens[idx] - g_dens[BN + idx];
    float c_den = dd * dd;

    float fro = 0.f;
#pragma unroll
    for (int s = 0; s < 6; s++) {
        float e = g_cov[s*BN + idx] - g_cov[(6 + s)*BN + idx];
        float w = (s < 3) ? 1.0f : 2.0f;
        fro = fmaf(w * e, e, fro);
    }
    float c_cur = sqrtf(fro);

    float dsum = 0.f;
#pragma unroll
    for (int e = 0; e < Kk * 3; e++)
        dsum = fmaf(g_nv[e*BN + idx], g_nv[(Kk*3 + e)*BN + idx], dsum);

    __shared__ float r[3 * CTPB];
    r[tid]          = c_den;
    r[CTPB + tid]   = dsum;
    r[2*CTPB + tid] = c_cur;
    __syncthreads();
#pragma unroll
    for (int s = CTPB / 2; s > 0; s >>= 1) {
        if (tid < s) {
            r[tid]          += r[tid + s];
            r[CTPB + tid]   += r[CTPB + tid + s];
            r[2*CTPB + tid] += r[2*CTPB + tid + s];
        }
        __syncthreads();
    }
    if (tid == 0) {
        g_part[blockIdx.x]        = r[0];
        g_part[CB + blockIdx.x]   = r[CTPB];
        g_part[2*CB + blockIdx.x] = r[2*CTPB];
    }
}

__global__ void __launch_bounds__(CB) finalize_kernel(float* __restrict__ out) {
    __shared__ float r[3 * CB];
    int tid = threadIdx.x;
    r[tid]        = g_part[tid];
    r[CB + tid]   = g_part[CB + tid];
    r[2*CB + tid] = g_part[2*CB + tid];
    __syncthreads();
#pragma unroll
    for (int s = CB / 2; s > 0; s >>= 1) {
        if (tid < s) {
            r[tid]        += r[tid + s];
            r[CB + tid]   += r[CB + tid + s];
            r[2*CB + tid] += r[2*CB + tid + s];
        }
        __syncthreads();
    }
    if (tid == 0) {
        const float invBN = 1.0f / (float)BN;
        float density_loss   = r[0] * invBN;
        float direction_loss = 1.0f - r[CB] * (invBN / (float)Kk);
        float curvature_loss = r[2*CB] * invBN;
        out[0] = density_loss + 0.5f * direction_loss + 0.5f * curvature_loss;
    }
}

extern "C" void kernel_launch(void* const* d_in, const int* in_sizes, int n_in,
                              void* d_out, int out_size) {
    (void)in_sizes; (void)n_in; (void)out_size;
    const float* pred   = (const float*)d_in[0];
    const float* target = (const float*)d_in[1];

    size_t smem_bytes = (size_t)Nn * sizeof(float4)
                      + (size_t)3 * PPB * 9 * (sizeof(float) + sizeof(int)); // ~118 KB
    cudaFuncSetAttribute(knn_scan_kernel,
                         cudaFuncAttributeMaxDynamicSharedMemorySize,
                         (int)smem_bytes);

    dim3 grid(Nn / PPB, Bb, 2);                 // 128 blocks, 1024 threads each
    knn_scan_kernel<<<grid, TPB, smem_bytes>>>(pred, target);
    combine_kernel<<<CB, CTPB>>>();
    finalize_kernel<<<1, CB>>>((float*)d_out);
}

// round 9
// speedup vs baseline: 1.0997x; 1.0997x over previous
#include <cuda_runtime.h>

#define Nn    4096
#define Bb    4
#define Kk    8
#define BN    (Bb * Nn)         // 16384 points per cloud
#define TPB   512               // 256 points/block, 2 threads per point
#define PPB   256               // points per block
#define NPAIR (Nn / 2)          // 2048 packed candidate pairs
#define HALFP (NPAIR / 2)       // 1024 pairs per thread
#define CB    64
#define CTPB  256
#define EPSF  1e-12f

typedef unsigned long long u64;

#define FMA2(out,a,b,c)  asm("fma.rn.f32x2 %0, %1, %2, %3;" : "=l"(out) : "l"(a), "l"(b), "l"(c))
#define PACK2(out,lo,hi) asm("mov.b64 %0, {%1, %2};" : "=l"(out) : "f"(lo), "f"(hi))
#define UNPACK2(lo,hi,in) asm("mov.b64 {%0, %1}, %2;" : "=f"(lo), "=f"(hi) : "l"(in))

// ---- device scratch (SoA, coalesced) ----
__device__ float g_dens[2 * BN];
__device__ float g_cov [2 * 6 * BN];
__device__ float g_nv  [2 * Kk * 3 * BN];
__device__ float g_part[3 * CB];

// Two-tier sorted insert of (v, j) into ascending 9-list. Warp-uniform branches.
__device__ __forceinline__ void insert9(float bd[9], int bi[9], float v, int j) {
    if (__any_sync(0xffffffffu, v < bd[2])) {      // rare: deep insert
        bool c[9];
#pragma unroll
        for (int t = 0; t < 9; t++) c[t] = v < bd[t];
#pragma unroll
        for (int t = 8; t >= 1; t--) {
            bd[t] = c[t] ? (c[t-1] ? bd[t-1] : v) : bd[t];
            bi[t] = c[t] ? (c[t-1] ? bi[t-1] : j) : bi[t];
        }
        bd[0] = c[0] ? v : bd[0];
        bi[0] = c[0] ? j : bi[0];
    } else {                                        // common: all lanes v >= bd[2]
        bool c[9];
#pragma unroll
        for (int t = 3; t < 9; t++) c[t] = v < bd[t];
#pragma unroll
        for (int t = 8; t >= 4; t--) {
            bd[t] = c[t] ? (c[t-1] ? bd[t-1] : v) : bd[t];
            bi[t] = c[t] ? (c[t-1] ? bi[t-1] : j) : bi[t];
        }
        bd[3] = c[3] ? v : bd[3];
        bi[3] = c[3] ? j : bi[3];
    }
}

// Scan HALFP candidate pairs starting at pair p0; keep 9 smallest squared
// distances ascending (ties -> lower index via strict < and monotone j).
__device__ __forceinline__ void scan9(const float4* __restrict__ sxy,
                                      const float4* __restrict__ szw,
                                      int p0, u64 m2x2, u64 m2y2, u64 m2z2,
                                      float sq, float bd[9], int bi[9]) {
#pragma unroll
    for (int t = 0; t < 9; t++) { bd[t] = 3.4e38f; bi[t] = 0; }
    float thr = 3.4e38f;                // = bd[8] - sq, in d2' space
    const int pend = p0 + HALFP;
#pragma unroll 2
    for (int p = p0; p < pend; p++) {
        float4 qxy = sxy[p];            // {x0, x1, y0, y1}
        float4 qzw = szw[p];            // {z0, z1, w0, w1}
        u64 x01, y01, z01, w01, acc;
        PACK2(x01, qxy.x, qxy.y);
        PACK2(y01, qxy.z, qxy.w);
        PACK2(z01, qzw.x, qzw.y);
        PACK2(w01, qzw.z, qzw.w);
        FMA2(acc, m2z2, z01, w01);      // d2' = w - 2<p,q> (both candidates)
        FMA2(acc, m2y2, y01, acc);
        FMA2(acc, m2x2, x01, acc);
        float lo, hi;
        UNPACK2(lo, hi, acc);
        float mn = fminf(lo, hi);
        if (__any_sync(0xffffffffu, mn < thr)) {
            if (__any_sync(0xffffffffu, lo < thr)) insert9(bd, bi, lo + sq, 2*p);
            if (__any_sync(0xffffffffu, hi < thr)) insert9(bd, bi, hi + sq, 2*p + 1);
            thr = bd[8] - sq;
        }
    }
}

// Merge sorted 9-list (smem) into (bd,bi); ties prefer (bd,bi) (lower index).
__device__ __forceinline__ void merge9(float bd[9], int bi[9],
                                       const float* __restrict__ ld,
                                       const int*   __restrict__ li) {
    float ed[9]; int ei[9];
#pragma unroll
    for (int t = 0; t < 9; t++) { ed[t] = ld[t]; ei[t] = li[t]; }
    float od[9]; int oi[9];
#pragma unroll
    for (int r = 0; r < 9; r++) {
        bool ta = bd[0] <= ed[0];
        od[r] = ta ? bd[0] : ed[0];
        oi[r] = ta ? bi[0] : ei[0];
#pragma unroll
        for (int t = 0; t < 8; t++) {
            bd[t] = ta ? bd[t+1] : bd[t];
            bi[t] = ta ? bi[t+1] : bi[t];
            ed[t] = ta ? ed[t]   : ed[t+1];
            ei[t] = ta ? ei[t]   : ei[t+1];
        }
        bd[8] = ta ? 3.4e38f : bd[8];
        ed[8] = ta ? ed[8]   : 3.4e38f;
    }
#pragma unroll
    for (int t = 0; t < 9; t++) { bd[t] = od[t]; bi[t] = oi[t]; }
}

// Fetch point j from paired-SoA smem.
__device__ __forceinline__ void fetch_pt(const float4* sxy, const float4* szw,
                                         int j, float& x, float& y, float& z, float& w) {
    int p = j >> 1, h = j & 1;
    float4 a = sxy[p], b = szw[p];
    x = h ? a.y : a.x;
    y = h ? a.w : a.z;
    z = h ? b.y : b.x;
    w = h ? b.w : b.z;
}

// Block: 256 points of one (batch, cloud), 2 threads/point (candidate halves).
__global__ void __launch_bounds__(TPB)
knn_scan_kernel(const float* __restrict__ pred, const float* __restrict__ target) {
    extern __shared__ char smem_raw[];
    float4* sxy  = (float4*)smem_raw;                          // [NPAIR]
    float4* szw  = sxy + NPAIR;                                // [NPAIR]
    float*  lstd = (float*)(szw + NPAIR);                      // [PPB*9]
    int*    lsti = (int*)(lstd + PPB * 9);                     // [PPB*9]

    const int tid  = threadIdx.x;
    const int b    = blockIdx.y;
    const int c    = blockIdx.z;             // 0 = pred, 1 = target
    const int pl   = tid & (PPB - 1);        // local point
    const int half = tid >> 8;               // candidate half 0/1

    const float* src = (c == 0 ? pred : target) + (size_t)b * Nn * 3;
    for (int p = tid; p < NPAIR; p += TPB) {
        const float* s0 = src + 6 * p;
        float x0 = s0[0], y0 = s0[1], z0 = s0[2];
        float x1 = s0[3], y1 = s0[4], z1 = s0[5];
        float w0 = fmaf(x0, x0, fmaf(y0, y0, z0 * z0));
        float w1 = fmaf(x1, x1, fmaf(y1, y1, z1 * z1));
        sxy[p] = make_float4(x0, x1, y0, y1);
        szw[p] = make_float4(z0, z1, w0, w1);
    }
    __syncthreads();

    const int i = blockIdx.x * PPB + pl;
    float px, py, pz, sq;
    fetch_pt(sxy, szw, i, px, py, pz, sq);

    u64 m2x2, m2y2, m2z2;
    {
        float mx = -2.0f * px, my = -2.0f * py, mz = -2.0f * pz;
        PACK2(m2x2, mx, mx);
        PACK2(m2y2, my, my);
        PACK2(m2z2, mz, mz);
    }

    float bd[9]; int bi[9];
    scan9(sxy, szw, half * HALFP, m2x2, m2y2, m2z2, sq, bd, bi);

    // half-B publishes its sorted list (stride-9 -> conflict-free)
    if (half == 1) {
        float* dd = lstd + pl * 9;
        int*   ii = lsti + pl * 9;
#pragma unroll
        for (int t = 0; t < 9; t++) { dd[t] = bd[t]; ii[t] = bi[t]; }
    }
    __syncthreads();
    if (half == 1) return;

    merge9(bd, bi, lstd + pl * 9, lsti + pl * 9);

    // ---- epilogue: density, covariance, normalized neighbor vectors ----
    const int base = b * Nn + i;
    float dens = 0.f;
    float cxx = 0.f, cyy = 0.f, czz = 0.f, cxy = 0.f, cxz = 0.f, cyz = 0.f;
#pragma unroll
    for (int k = 0; k < Kk; k++) {
        dens += sqrtf(fmaxf(bd[k+1], EPSF));
        float qx, qy, qz, qw;
        fetch_pt(sxy, szw, bi[k+1], qx, qy, qz, qw);
        float vx = qx - px, vy = qy - py, vz = qz - pz;
        cxx = fmaf(vx, vx, cxx); cyy = fmaf(vy, vy, cyy); czz = fmaf(vz, vz, czz);
        cxy = fmaf(vx, vy, cxy); cxz = fmaf(vx, vz, cxz); cyz = fmaf(vy, vz, cyz);
        float nrm = sqrtf(fmaf(vx, vx, fmaf(vy, vy, vz * vz)));
        float inv = 1.0f / fmaxf(nrm, EPSF);
        g_nv[((c*Kk + k)*3 + 0)*BN + base] = vx * inv;
        g_nv[((c*Kk + k)*3 + 1)*BN + base] = vy * inv;
        g_nv[((c*Kk + k)*3 + 2)*BN + base] = vz * inv;
    }
    g_dens[c*BN + base]        = dens * 0.125f;
    g_cov[(c*6 + 0)*BN + base] = cxx * 0.125f;
    g_cov[(c*6 + 1)*BN + base] = cyy * 0.125f;
    g_cov[(c*6 + 2)*BN + base] = czz * 0.125f;
    g_cov[(c*6 + 3)*BN + base] = cxy * 0.125f;
    g_cov[(c*6 + 4)*BN + base] = cxz * 0.125f;
    g_cov[(c*6 + 5)*BN + base] = cyz * 0.125f;
}

// Pair pred/target stats per point, partial-reduce per block.
__global__ void __launch_bounds__(CTPB)
combine_kernel() {
    const int tid = threadIdx.x;
    const int idx = blockIdx.x * CTPB + tid;

    float dd = g_dens[idx] - g_dens[BN + idx];
    float c_den = dd * dd;

    float fro = 0.f;
#pragma unroll
    for (int s = 0; s < 6; s++) {
        float e = g_cov[s*BN + idx] - g_cov[(6 + s)*BN + idx];
        float w = (s < 3) ? 1.0f : 2.0f;
        fro = fmaf(w * e, e, fro);
    }
    float c_cur = sqrtf(fro);

    float dsum = 0.f;
#pragma unroll
    for (int e = 0; e < Kk * 3; e++)
        dsum = fmaf(g_nv[e*BN + idx], g_nv[(Kk*3 + e)*BN + idx], dsum);

    __shared__ float r[3 * CTPB];
    r[tid]          = c_den;
    r[CTPB + tid]   = dsum;
    r[2*CTPB + tid] = c_cur;
    __syncthreads();
#pragma unroll
    for (int s = CTPB / 2; s > 0; s >>= 1) {
        if (tid < s) {
            r[tid]          += r[tid + s];
            r[CTPB + tid]   += r[CTPB + tid + s];
            r[2*CTPB + tid] += r[2*CTPB + tid + s];
        }
        __syncthreads();
    }
    if (tid == 0) {
        g_part[blockIdx.x]        = r[0];
        g_part[CB + blockIdx.x]   = r[CTPB];
        g_part[2*CB + blockIdx.x] = r[2*CTPB];
    }
}

__global__ void __launch_bounds__(CB) finalize_kernel(float* __restrict__ out) {
    __shared__ float r[3 * CB];
    int tid = threadIdx.x;
    r[tid]        = g_part[tid];
    r[CB + tid]   = g_part[CB + tid];
    r[2*CB + tid] = g_part[2*CB + tid];
    __syncthreads();
#pragma unroll
    for (int s = CB / 2; s > 0; s >>= 1) {
        if (tid < s) {
            r[tid]        += r[tid + s];
            r[CB + tid]   += r[CB + tid + s];
            r[2*CB + tid] += r[2*CB + tid + s];
        }
        __syncthreads();
    }
    if (tid == 0) {
        const float invBN = 1.0f / (float)BN;
        float density_loss   = r[0] * invBN;
        float direction_loss = 1.0f - r[CB] * (invBN / (float)Kk);
        float curvature_loss = r[2*CB] * invBN;
        out[0] = density_loss + 0.5f * direction_loss + 0.5f * curvature_loss;
    }
}

extern "C" void kernel_launch(void* const* d_in, const int* in_sizes, int n_in,
                              void* d_out, int out_size) {
    (void)in_sizes; (void)n_in; (void)out_size;
    const float* pred   = (const float*)d_in[0];
    const float* target = (const float*)d_in[1];

    size_t smem_bytes = (size_t)2 * NPAIR * sizeof(float4)
                      + (size_t)PPB * 9 * (sizeof(float) + sizeof(int)); // ~82 KB
    cudaFuncSetAttribute(knn_scan_kernel,
                         cudaFuncAttributeMaxDynamicSharedMemorySize,
                         (int)smem_bytes);

    dim3 grid(Nn / PPB, Bb, 2);                 // 128 blocks, 512 threads each
    knn_scan_kernel<<<grid, TPB, smem_bytes>>>(pred, target);
    combine_kernel<<<CB, CTPB>>>();
    finalize_kernel<<<1, CB>>>((float*)d_out);
}